// round 1
// baseline (speedup 1.0000x reference)
#include <cuda_runtime.h>
#include <cstdint>

// Problem constants (B=2, S=2048, D=1024, E=8, I=1408, TOPK=2)
#define TTOK 4096
#define DDIM 1024
#define ENUM 8
#define IDIM 1408

// GEMM tiling
#define BM 128
#define BN 64
#define BK 16
#define LDSS 20   // smem row stride in floats (16 + 4 pad, keeps 16B alignment)

// ---------------- static device scratch (no allocations allowed) ----------------
__device__ int   g_cnt[ENUM];
__device__ int   g_tok[ENUM * TTOK];
__device__ int   g_slot[ENUM * TTOK];
__device__ float g_prob[ENUM * TTOK];
__device__ float g_h[(size_t)ENUM * TTOK * IDIM];    // silu(g)*u*prob, expert-major
__device__ float g_yp[(size_t)2 * TTOK * DDIM];      // per-slot partial outputs

// ---------------- helpers ----------------
__device__ __forceinline__ uint32_t f2tf(float f) {
    uint32_t r;
    asm("cvt.rna.tf32.f32 %0, %1;" : "=r"(r) : "f"(f));
    return r;
}

__device__ __forceinline__ void mma8(float* c, const uint32_t* a, uint32_t b0, uint32_t b1) {
    asm volatile(
        "mma.sync.aligned.m16n8k8.row.col.f32.tf32.tf32.f32 "
        "{%0,%1,%2,%3},{%4,%5,%6,%7},{%8,%9},{%0,%1,%2,%3};\n"
        : "+f"(c[0]), "+f"(c[1]), "+f"(c[2]), "+f"(c[3])
        : "r"(a[0]), "r"(a[1]), "r"(a[2]), "r"(a[3]), "r"(b0), "r"(b1));
}

__device__ __forceinline__ void cpa16(void* s, const void* g) {
    uint32_t sa = (uint32_t)__cvta_generic_to_shared(s);
    asm volatile("cp.async.cg.shared.global [%0], [%1], 16;\n" :: "r"(sa), "l"(g));
}
__device__ __forceinline__ void cpa_commit() { asm volatile("cp.async.commit_group;\n"); }
template <int N>
__device__ __forceinline__ void cpa_wait() { asm volatile("cp.async.wait_group %0;\n" :: "n"(N)); }

// ---------------- kernel 0: reset per-launch state ----------------
__global__ void k_zero() {
    if (threadIdx.x < ENUM) g_cnt[threadIdx.x] = 0;
}

// ---------------- kernel 1: router (scores, top-2, softmax, bucket) ----------------
__global__ void k_router(const float* __restrict__ x, const float* __restrict__ gw) {
    int gwarp = (blockIdx.x * blockDim.x + threadIdx.x) >> 5;
    int lane = threadIdx.x & 31;
    if (gwarp >= TTOK) return;

    const float4* xr = (const float4*)(x + (size_t)gwarp * DDIM);
    const float4* g4 = (const float4*)gw;

    float acc[ENUM];
#pragma unroll
    for (int e = 0; e < ENUM; e++) acc[e] = 0.f;

    for (int c = lane; c < DDIM / 4; c += 32) {
        float4 xv = xr[c];
#pragma unroll
        for (int e = 0; e < ENUM; e++) {
            float4 wv = g4[e * (DDIM / 4) + c];
            acc[e] += xv.x * wv.x + xv.y * wv.y + xv.z * wv.z + xv.w * wv.w;
        }
    }
#pragma unroll
    for (int e = 0; e < ENUM; e++) {
#pragma unroll
        for (int off = 16; off > 0; off >>= 1)
            acc[e] += __shfl_xor_sync(0xFFFFFFFFu, acc[e], off);
    }

    if (lane == 0) {
        int i0 = 0;
        float s0 = acc[0];
#pragma unroll
        for (int e = 1; e < ENUM; e++)
            if (acc[e] > s0) { s0 = acc[e]; i0 = e; }
        int i1 = -1;
        float s1 = -3.4e38f;
#pragma unroll
        for (int e = 0; e < ENUM; e++)
            if (e != i0 && acc[e] > s1) { s1 = acc[e]; i1 = e; }

        // softmax over the two selected scores (max-subtracted, like jax)
        float e1 = expf(s1 - s0);
        float inv = 1.f / (1.f + e1);
        float p0 = inv;
        float p1 = e1 * inv;

        int pos0 = atomicAdd(&g_cnt[i0], 1);
        g_tok[i0 * TTOK + pos0]  = gwarp;
        g_slot[i0 * TTOK + pos0] = 0;
        g_prob[i0 * TTOK + pos0] = p0;

        int pos1 = atomicAdd(&g_cnt[i1], 1);
        g_tok[i1 * TTOK + pos1]  = gwarp;
        g_slot[i1 * TTOK + pos1] = 1;
        g_prob[i1 * TTOK + pos1] = p1;
    }
}

// ---------------- kernel 2: gathered gate+up GEMMs, fused silu*u*prob -> g_h ----------
// Per block: 128 gathered token rows x 64 I-columns, K=1024, both Wg and Wu.
__global__ __launch_bounds__(256, 1) void k_ffn1(
    const float* __restrict__ x, const float* __restrict__ wg, const float* __restrict__ wu) {
    __shared__ float sX[2][BM * LDSS];
    __shared__ float sG[2][BN * LDSS];
    __shared__ float sU[2][BN * LDSS];
    __shared__ int   sTok[BM];
    __shared__ float sProb[BM];

    const int e = blockIdx.z;
    const int cnt = g_cnt[e];
    const int m0 = blockIdx.y * BM;
    if (m0 >= cnt) return;
    const int n0 = blockIdx.x * BN;
    const int tid = threadIdx.x;

    if (tid < BM) {
        int rc = min(m0 + tid, cnt - 1);
        sTok[tid]  = g_tok[e * TTOK + rc];
        sProb[tid] = g_prob[e * TTOK + rc];
    }
    __syncthreads();

    const int lane = tid & 31;
    const int wid = tid >> 5;
    const int wm0 = (wid & 3) * 32;   // 4 warps over M
    const int wn0 = (wid >> 2) * 32;  // 2 warps over N

    const float* wgb = wg + (size_t)e * IDIM * DDIM;
    const float* wub = wu + (size_t)e * IDIM * DDIM;

    auto load_tiles = [&](int st, int kt) {
        const int kbase = kt * BK;
        // X tile: 128 rows x 16 cols = 512 float4 chunks, 2 per thread
#pragma unroll
        for (int it = 0; it < 2; it++) {
            int f = tid + it * 256;
            int row = f >> 2, c4 = f & 3;
            const float* src = x + (size_t)sTok[row] * DDIM + kbase + c4 * 4;
            cpa16(&sX[st][row * LDSS + c4 * 4], src);
        }
        // W tiles: 64 rows x 16 cols = 256 float4 chunks each, 1 per thread
        int row = tid >> 2, c4 = tid & 3;
        size_t wo = (size_t)(n0 + row) * DDIM + kbase + c4 * 4;
        cpa16(&sG[st][row * LDSS + c4 * 4], wgb + wo);
        cpa16(&sU[st][row * LDSS + c4 * 4], wub + wo);
    };

    float cg[2][4][4], cu[2][4][4];
#pragma unroll
    for (int a = 0; a < 2; a++)
#pragma unroll
        for (int b = 0; b < 4; b++)
#pragma unroll
            for (int c = 0; c < 4; c++) { cg[a][b][c] = 0.f; cu[a][b][c] = 0.f; }

    load_tiles(0, 0);
    cpa_commit();

    const int KT = DDIM / BK;  // 64
    for (int kt = 0; kt < KT; kt++) {
        int cur = kt & 1;
        if (kt + 1 < KT) load_tiles(cur ^ 1, kt + 1);
        cpa_commit();
        cpa_wait<1>();
        __syncthreads();

        const float* pX = sX[cur];
        const float* pG = sG[cur];
        const float* pU = sU[cur];
#pragma unroll
        for (int ks = 0; ks < 2; ks++) {
            uint32_t af[2][4];
#pragma unroll
            for (int mt = 0; mt < 2; mt++) {
                int r = wm0 + mt * 16 + (lane >> 2);
                int c = ks * 8 + (lane & 3);
                af[mt][0] = f2tf(pX[r * LDSS + c]);
                af[mt][1] = f2tf(pX[(r + 8) * LDSS + c]);
                af[mt][2] = f2tf(pX[r * LDSS + c + 4]);
                af[mt][3] = f2tf(pX[(r + 8) * LDSS + c + 4]);
            }
#pragma unroll
            for (int nt = 0; nt < 4; nt++) {
                int bn = wn0 + nt * 8 + (lane >> 2);
                int bk = ks * 8 + (lane & 3);
                uint32_t bg0 = f2tf(pG[bn * LDSS + bk]);
                uint32_t bg1 = f2tf(pG[bn * LDSS + bk + 4]);
                uint32_t bu0 = f2tf(pU[bn * LDSS + bk]);
                uint32_t bu1 = f2tf(pU[bn * LDSS + bk + 4]);
#pragma unroll
                for (int mt = 0; mt < 2; mt++) {
                    mma8(cg[mt][nt], af[mt], bg0, bg1);
                    mma8(cu[mt][nt], af[mt], bu0, bu1);
                }
            }
        }
        __syncthreads();
    }

    // epilogue: h = silu(g) * u * prob
#pragma unroll
    for (int mt = 0; mt < 2; mt++) {
#pragma unroll
        for (int nt = 0; nt < 4; nt++) {
#pragma unroll
            for (int k = 0; k < 4; k++) {
                int rl = wm0 + mt * 16 + (lane >> 2) + ((k >= 2) ? 8 : 0);
                int col = n0 + wn0 + nt * 8 + 2 * (lane & 3) + (k & 1);
                if (m0 + rl < cnt) {
                    float g = cg[mt][nt][k];
                    float u = cu[mt][nt][k];
                    float h = (g / (1.f + expf(-g))) * u * sProb[rl];
                    g_h[((size_t)e * TTOK + m0 + rl) * IDIM + col] = h;
                }
            }
        }
    }
}

// ---------------- kernel 3: down-proj GEMM, scatter into per-slot partials -----------
__global__ __launch_bounds__(256, 1) void k_ffn2(const float* __restrict__ wd) {
    __shared__ float sH[2][BM * LDSS];
    __shared__ float sW[2][BN * LDSS];
    __shared__ int   sTok[BM];
    __shared__ int   sSlot[BM];

    const int e = blockIdx.z;
    const int cnt = g_cnt[e];
    const int m0 = blockIdx.y * BM;
    if (m0 >= cnt) return;
    const int n0 = blockIdx.x * BN;
    const int tid = threadIdx.x;

    if (tid < BM) {
        int rc = min(m0 + tid, cnt - 1);
        sTok[tid]  = g_tok[e * TTOK + rc];
        sSlot[tid] = g_slot[e * TTOK + rc];
    }
    __syncthreads();

    const int lane = tid & 31;
    const int wid = tid >> 5;
    const int wm0 = (wid & 3) * 32;
    const int wn0 = (wid >> 2) * 32;

    const float* hb = g_h + (size_t)e * TTOK * IDIM;
    const float* wdb = wd + (size_t)e * DDIM * IDIM;

    auto load_tiles = [&](int st, int kt) {
        const int kbase = kt * BK;
#pragma unroll
        for (int it = 0; it < 2; it++) {
            int f = tid + it * 256;
            int row = f >> 2, c4 = f & 3;
            int rc = min(m0 + row, cnt - 1);
            const float* src = hb + (size_t)rc * IDIM + kbase + c4 * 4;
            cpa16(&sH[st][row * LDSS + c4 * 4], src);
        }
        int row = tid >> 2, c4 = tid & 3;
        const float* src = wdb + (size_t)(n0 + row) * IDIM + kbase + c4 * 4;
        cpa16(&sW[st][row * LDSS + c4 * 4], src);
    };

    float cc[2][4][4];
#pragma unroll
    for (int a = 0; a < 2; a++)
#pragma unroll
        for (int b = 0; b < 4; b++)
#pragma unroll
            for (int c = 0; c < 4; c++) cc[a][b][c] = 0.f;

    load_tiles(0, 0);
    cpa_commit();

    const int KT = IDIM / BK;  // 88
    for (int kt = 0; kt < KT; kt++) {
        int cur = kt & 1;
        if (kt + 1 < KT) load_tiles(cur ^ 1, kt + 1);
        cpa_commit();
        cpa_wait<1>();
        __syncthreads();

        const float* pH = sH[cur];
        const float* pW = sW[cur];
#pragma unroll
        for (int ks = 0; ks < 2; ks++) {
            uint32_t af[2][4];
#pragma unroll
            for (int mt = 0; mt < 2; mt++) {
                int r = wm0 + mt * 16 + (lane >> 2);
                int c = ks * 8 + (lane & 3);
                af[mt][0] = f2tf(pH[r * LDSS + c]);
                af[mt][1] = f2tf(pH[(r + 8) * LDSS + c]);
                af[mt][2] = f2tf(pH[r * LDSS + c + 4]);
                af[mt][3] = f2tf(pH[(r + 8) * LDSS + c + 4]);
            }
#pragma unroll
            for (int nt = 0; nt < 4; nt++) {
                int bn = wn0 + nt * 8 + (lane >> 2);
                int bk = ks * 8 + (lane & 3);
                uint32_t b0 = f2tf(pW[bn * LDSS + bk]);
                uint32_t b1 = f2tf(pW[bn * LDSS + bk + 4]);
#pragma unroll
                for (int mt = 0; mt < 2; mt++)
                    mma8(cc[mt][nt], af[mt], b0, b1);
            }
        }
        __syncthreads();
    }

#pragma unroll
    for (int mt = 0; mt < 2; mt++) {
#pragma unroll
        for (int nt = 0; nt < 4; nt++) {
#pragma unroll
            for (int k = 0; k < 4; k++) {
                int rl = wm0 + mt * 16 + (lane >> 2) + ((k >= 2) ? 8 : 0);
                int col = n0 + wn0 + nt * 8 + 2 * (lane & 3) + (k & 1);
                if (m0 + rl < cnt) {
                    int tok = sTok[rl];
                    int sl = sSlot[rl];
                    g_yp[((size_t)sl * TTOK + tok) * DDIM + col] = cc[mt][nt][k];
                }
            }
        }
    }
}

// ---------------- kernel 4: combine slot partials -> output ----------------
__global__ void k_combine(float* __restrict__ out) {
    int i = blockIdx.x * blockDim.x + threadIdx.x;  // float4 index, total T*D/4
    const float4* a = (const float4*)g_yp;
    const float4* b = (const float4*)(g_yp + (size_t)TTOK * DDIM);
    float4 va = a[i], vb = b[i];
    float4 o;
    o.x = va.x + vb.x;
    o.y = va.y + vb.y;
    o.z = va.z + vb.z;
    o.w = va.w + vb.w;
    ((float4*)out)[i] = o;
}

// ---------------- launch ----------------
extern "C" void kernel_launch(void* const* d_in, const int* in_sizes, int n_in,
                              void* d_out, int out_size) {
    const float* x  = (const float*)d_in[0];
    const float* gw = (const float*)d_in[1];
    const float* wg = (const float*)d_in[2];
    const float* wu = (const float*)d_in[3];
    const float* wd = (const float*)d_in[4];

    k_zero<<<1, 32>>>();
    k_router<<<TTOK / 8, 256>>>(x, gw);

    dim3 gA(IDIM / BN, TTOK / BM, ENUM);  // (22, 32, 8)
    k_ffn1<<<gA, 256>>>(x, wg, wu);

    dim3 gB(DDIM / BN, TTOK / BM, ENUM);  // (16, 32, 8)
    k_ffn2<<<gB, 256>>>(wd);

    k_combine<<<(TTOK * DDIM / 4) / 256, 256>>>((float*)d_out);
}